// round 15
// baseline (speedup 1.0000x reference)
#include <cuda_runtime.h>
#include <cuda_bf16.h>
#include <cstdint>

// Problem constants
#define BB 2
#define SS 2048
#define DD 1024
#define HH 16
#define HD 64
#define MROWS (BB*SS)          // 4096
#define X_ELEMS (BB*SS*DD)     // 4194304
#define ATT_ELEMS (BB*HH*SS*SS)// 134217728

// ---------------- scratch (device globals: allocation-free) ----------------
__device__ __nv_bfloat16 g_Qh[MROWS*DD], g_Ql[MROWS*DD]; // [BH][S][HD]
__device__ __nv_bfloat16 g_Kh[MROWS*DD], g_Kl[MROWS*DD]; // [BH][S][HD]
__device__ __nv_bfloat16 g_Vh[MROWS*DD], g_Vl[MROWS*DD]; // [BH][S][HD]
__device__ __nv_bfloat16 g_Ch[MROWS*DD], g_Cl[MROWS*DD]; // ctx [B][S][D]
__device__ __nv_bfloat16 g_Ah[MROWS*DD], g_Al[MROWS*DD]; // gemm input staging
__device__ __nv_bfloat16 g_Wh[DD*DD],    g_Wl[DD*DD];    // gemm weight staging

// ---------------- mma.sync / ldmatrix helpers (baseline ISA, sm_80+) -------
__device__ __forceinline__ uint32_t smem_u32(const void* p) {
    uint32_t a;
    asm("{ .reg .u64 t; cvta.to.shared.u64 t, %1; cvt.u32.u64 %0, t; }"
        : "=r"(a) : "l"(p));
    return a;
}
#define LDSM4(r, a)                                                          \
    asm volatile("ldmatrix.sync.aligned.m8n8.x4.shared.b16 {%0,%1,%2,%3}, [%4];" \
        : "=r"((r)[0]), "=r"((r)[1]), "=r"((r)[2]), "=r"((r)[3]) : "r"(a) : "memory")
#define LDSM2(r, a)                                                          \
    asm volatile("ldmatrix.sync.aligned.m8n8.x2.shared.b16 {%0,%1}, [%2];"   \
        : "=r"((r)[0]), "=r"((r)[1]) : "r"(a) : "memory")
#define LDSM2T(r, a)                                                         \
    asm volatile("ldmatrix.sync.aligned.m8n8.x2.trans.shared.b16 {%0,%1}, [%2];" \
        : "=r"((r)[0]), "=r"((r)[1]) : "r"(a) : "memory")
#define MMA_BF16(c, a, b0, b1)                                               \
    asm volatile("mma.sync.aligned.m16n8k16.row.col.f32.bf16.bf16.f32 "      \
        "{%0,%1,%2,%3}, {%4,%5,%6,%7}, {%8,%9}, {%0,%1,%2,%3};"              \
        : "+f"((c)[0]), "+f"((c)[1]), "+f"((c)[2]), "+f"((c)[3])             \
        : "r"((a)[0]), "r"((a)[1]), "r"((a)[2]), "r"((a)[3]),                \
          "r"(b0), "r"(b1))

// hi/lo bf16 split of two floats -> packed bf16x2 words
__device__ __forceinline__ void split2(float a, float b, uint32_t &h, uint32_t &l) {
    __nv_bfloat162 hb = __floats2bfloat162_rn(a, b);
    float2 hf = __bfloat1622float2(hb);
    __nv_bfloat162 lb = __floats2bfloat162_rn(a - hf.x, b - hf.y);
    h = *reinterpret_cast<uint32_t*>(&hb);
    l = *reinterpret_cast<uint32_t*>(&lb);
}

// ---------------- fsplit: fp32 -> bf16 hi/lo (elementwise) ------------------
__global__ __launch_bounds__(256)
void fsplit(const float* __restrict__ x, __nv_bfloat16* __restrict__ h,
            __nv_bfloat16* __restrict__ l, int n4)
{
    int i = blockIdx.x * 256 + threadIdx.x;   // 4 floats per thread
    if (i < n4) {
        float4 v = ((const float4*)x)[i];
        uint32_t h0, h1, l0, l1;
        split2(v.x, v.y, h0, l0);
        split2(v.z, v.w, h1, l1);
        ((uint2*)h)[i] = make_uint2(h0, h1);
        ((uint2*)l)[i] = make_uint2(l0, l1);
    }
}

// ---------------- gemm_mma: C[m][n] = sum_k A[m][k]*W[n][k] + bias[n] ------
// bf16 hi/lo 3-product mma.sync. M=4096, N=1024, K=1024.
// 128x128 block, 256 threads, 8 warps (4m x 2n), warp tile 32x64, k-chunk 64.
// mode 0: bias + split-scatter to [B*H][S][HD] hi/lo (QKV projections)
// mode 1: bias + fp32 [M][N] row-major (O projection)
#define SOFF(row, ch) ((uint32_t)((row) * 128 + (((ch) ^ ((row) & 7)) << 4)))
#define G_AH 0
#define G_AL 16384
#define G_WH 32768
#define G_WL 49152
#define GEMM_SMEM 65536

__global__ __launch_bounds__(256, 2)
void gemm_mma(const __nv_bfloat16* __restrict__ Ah, const __nv_bfloat16* __restrict__ Al,
              const float* __restrict__ bias, float* __restrict__ out,
              __nv_bfloat16* __restrict__ outH, __nv_bfloat16* __restrict__ outL,
              int mode)
{
    extern __shared__ char sm[];
    uint32_t sb = smem_u32(sm);

    int tid = threadIdx.x, w = tid >> 5, lane = tid & 31;
    int g = lane >> 2, t = lane & 3;
    int m0 = blockIdx.y << 7;
    int n0 = blockIdx.x << 7;
    int wm = w >> 1, wn = w & 1;

    float acc[2][8][4];
#pragma unroll
    for (int mi = 0; mi < 2; mi++)
#pragma unroll
        for (int nj = 0; nj < 8; nj++)
#pragma unroll
            for (int x = 0; x < 4; x++) acc[mi][nj][x] = 0.f;

    // per-lane frag addresses
    int arow = wm * 32 + (lane & 15);
    int ach  = lane >> 4;
    int brow = wn * 64 + ((lane >> 4) & 1) * 8 + (lane & 7);
    int bch  = (lane >> 3) & 1;

    for (int kc = 0; kc < 16; kc++) {
        int k0 = kc << 6;
        __syncthreads();
#pragma unroll 4
        for (int i = tid; i < 128 * 8; i += 256) {
            int r = i >> 3, c = i & 7;
            uint32_t so = SOFF(r, c);
            size_t ao = (size_t)(m0 + r) * DD + k0 + c * 8;
            size_t wo = (size_t)(n0 + r) * DD + k0 + c * 8;
            *(uint4*)(sm + G_AH + so) = *(const uint4*)(Ah + ao);
            *(uint4*)(sm + G_AL + so) = *(const uint4*)(Al + ao);
            *(uint4*)(sm + G_WH + so) = *(const uint4*)(g_Wh + wo);
            *(uint4*)(sm + G_WL + so) = *(const uint4*)(g_Wl + wo);
        }
        __syncthreads();

#pragma unroll
        for (int kk = 0; kk < 4; kk++) {
            uint32_t ah[2][4], al[2][4];
#pragma unroll
            for (int mi = 0; mi < 2; mi++) {
                uint32_t so = SOFF(arow + mi * 16, kk * 2 + ach);
                LDSM4(ah[mi], sb + G_AH + so);
                LDSM4(al[mi], sb + G_AL + so);
            }
#pragma unroll
            for (int njp = 0; njp < 4; njp++) {
                uint32_t so = SOFF(brow + njp * 16, kk * 2 + bch);
                uint32_t bh[4], bl[4];
                LDSM4(bh, sb + G_WH + so);
                LDSM4(bl, sb + G_WL + so);
#pragma unroll
                for (int mi = 0; mi < 2; mi++) {
                    MMA_BF16(acc[mi][njp*2],   ah[mi], bh[0], bh[1]);
                    MMA_BF16(acc[mi][njp*2],   ah[mi], bl[0], bl[1]);
                    MMA_BF16(acc[mi][njp*2],   al[mi], bh[0], bh[1]);
                    MMA_BF16(acc[mi][njp*2+1], ah[mi], bh[2], bh[3]);
                    MMA_BF16(acc[mi][njp*2+1], ah[mi], bl[2], bl[3]);
                    MMA_BF16(acc[mi][njp*2+1], al[mi], bh[2], bh[3]);
                }
            }
        }
    }

    // epilogue
#pragma unroll
    for (int mi = 0; mi < 2; mi++) {
        int r = m0 + wm * 32 + mi * 16 + g;     // rows r and r+8
#pragma unroll
        for (int nj = 0; nj < 8; nj++) {
            int c = n0 + wn * 64 + nj * 8 + t * 2;
            float b0 = bias[c], b1 = bias[c + 1];
            float v0 = acc[mi][nj][0] + b0, v1 = acc[mi][nj][1] + b1;
            float v2 = acc[mi][nj][2] + b0, v3 = acc[mi][nj][3] + b1;
            if (mode == 0) {
                int bb = r >> 11, s = r & 2047;
                int hh2 = c >> 6, hd = c & 63;
                size_t o0 = (((size_t)(bb * HH + hh2) * SS) + s) * HD + hd;
                size_t o1 = o0 + 8 * HD;        // row r+8 (same b, same head)
                uint32_t hw, lw;
                split2(v0, v1, hw, lw);
                *(uint32_t*)&outH[o0] = hw; *(uint32_t*)&outL[o0] = lw;
                split2(v2, v3, hw, lw);
                *(uint32_t*)&outH[o1] = hw; *(uint32_t*)&outL[o1] = lw;
            } else {
                *(float2*)&out[(size_t)r * DD + c]       = make_float2(v0, v1);
                *(float2*)&out[(size_t)(r + 8) * DD + c] = make_float2(v2, v3);
            }
        }
    }
}

// ---------------- mma.sync fused attention (passing R13 kernel) ------------
// Per CTA: one (b,h), 128 q rows, 8 warps (16 q rows each), NKT=32 k-tiles.
// Pass 1 = exact row sums; pass 2 = normalized attn write + PV.
// Epilogue now writes ctx as bf16 hi/lo (input to mma O-projection).
#define O_QH 0
#define O_QL 16384
#define O_KH 32768
#define O_KL 40960
#define O_VH 49152
#define O_VL 57344
#define O_MSK 65536
#define ATT_SMEM (65536 + 256)
#define NKT (SS / 64)   // 32

__global__ __launch_bounds__(256, 2)
void attn_mma(const int* __restrict__ mask, float* __restrict__ attn)
{
    extern __shared__ char sm[];
    uint32_t sb = smem_u32(sm);

    int tid = threadIdx.x, w = tid >> 5, lane = tid & 31;
    int g = lane >> 2, t = lane & 3;
    int bh = blockIdx.y, b = bh >> 4, h = bh & 15;
    int q0 = blockIdx.x << 7;

    // ---- load Q tile (128 x 64 bf16 hi/lo) ----
    size_t qb = ((size_t)bh * SS + q0) * HD;
#pragma unroll
    for (int i = tid; i < 128 * 8; i += 256) {
        int r = i >> 3, c = i & 7;
        uint32_t so = SOFF(r, c);
        *(uint4*)(sm + O_QH + so) = *(const uint4*)(g_Qh + qb + r * HD + c * 8);
        *(uint4*)(sm + O_QL + so) = *(const uint4*)(g_Ql + qb + r * HD + c * 8);
    }

    int qrow = w * 16 + (lane & 15);
    int qch  = lane >> 4;
    int krl  = lane & 7;
    int kch  = (lane >> 3) & 1;
    int vrl  = lane & 15;

    float rs0 = 0.f, rs1 = 0.f;

    // =================== PASS 1: exact row sums ===================
    for (int kt = 0; kt < NKT; kt++) {
        int k0 = kt << 6;
        size_t kb = ((size_t)bh * SS + k0) * HD;
        __syncthreads();
#pragma unroll
        for (int i = tid; i < 64 * 8; i += 256) {
            int r = i >> 3, c = i & 7;
            uint32_t so = SOFF(r, c);
            *(uint4*)(sm + O_KH + so) = *(const uint4*)(g_Kh + kb + r * HD + c * 8);
            *(uint4*)(sm + O_KL + so) = *(const uint4*)(g_Kl + kb + r * HD + c * 8);
        }
        if (tid < 64)
            ((float*)(sm + O_MSK))[tid] = mask[b * SS + k0 + tid] ? 1.f : 0.f;
        __syncthreads();

        float sacc[8][4];
#pragma unroll
        for (int j = 0; j < 8; j++)
#pragma unroll
            for (int x = 0; x < 4; x++) sacc[j][x] = 0.f;

#pragma unroll
        for (int kk = 0; kk < 4; kk++) {
            uint32_t ah[4], al[4];
            LDSM4(ah, sb + O_QH + SOFF(qrow, kk * 2 + qch));
            LDSM4(al, sb + O_QL + SOFF(qrow, kk * 2 + qch));
#pragma unroll
            for (int j = 0; j < 8; j++) {
                int krow = j * 8 + krl;
                uint32_t so = SOFF(krow, kk * 2 + kch);
                uint32_t bhr[2], blr[2];
                LDSM2(bhr, sb + O_KH + so);
                LDSM2(blr, sb + O_KL + so);
                MMA_BF16(sacc[j], ah, bhr[0], bhr[1]);
                MMA_BF16(sacc[j], ah, blr[0], blr[1]);
                MMA_BF16(sacc[j], al, bhr[0], bhr[1]);
            }
        }

        const float* mk = (const float*)(sm + O_MSK);
#pragma unroll
        for (int j = 0; j < 8; j++) {
            float m0 = mk[j * 8 + t * 2], m1 = mk[j * 8 + t * 2 + 1];
            rs0 += m0 * __expf(sacc[j][0] * 0.125f) + m1 * __expf(sacc[j][1] * 0.125f);
            rs1 += m0 * __expf(sacc[j][2] * 0.125f) + m1 * __expf(sacc[j][3] * 0.125f);
        }
    }
    rs0 += __shfl_xor_sync(0xffffffffu, rs0, 1);
    rs0 += __shfl_xor_sync(0xffffffffu, rs0, 2);
    rs1 += __shfl_xor_sync(0xffffffffu, rs1, 1);
    rs1 += __shfl_xor_sync(0xffffffffu, rs1, 2);
    float inv0 = 1.f / rs0, inv1 = 1.f / rs1;

    // =================== PASS 2: normalized attn + PV ===================
    float vacc[8][4];
#pragma unroll
    for (int j = 0; j < 8; j++)
#pragma unroll
        for (int x = 0; x < 4; x++) vacc[j][x] = 0.f;

    for (int kt = 0; kt < NKT; kt++) {
        int k0 = kt << 6;
        size_t kb = ((size_t)bh * SS + k0) * HD;
        __syncthreads();
#pragma unroll
        for (int i = tid; i < 64 * 8; i += 256) {
            int r = i >> 3, c = i & 7;
            uint32_t so = SOFF(r, c);
            *(uint4*)(sm + O_KH + so) = *(const uint4*)(g_Kh + kb + r * HD + c * 8);
            *(uint4*)(sm + O_KL + so) = *(const uint4*)(g_Kl + kb + r * HD + c * 8);
            *(uint4*)(sm + O_VH + so) = *(const uint4*)(g_Vh + kb + r * HD + c * 8);
            *(uint4*)(sm + O_VL + so) = *(const uint4*)(g_Vl + kb + r * HD + c * 8);
        }
        if (tid < 64)
            ((float*)(sm + O_MSK))[tid] = mask[b * SS + k0 + tid] ? 1.f : 0.f;
        __syncthreads();

        float sacc[8][4];
#pragma unroll
        for (int j = 0; j < 8; j++)
#pragma unroll
            for (int x = 0; x < 4; x++) sacc[j][x] = 0.f;
#pragma unroll
        for (int kk = 0; kk < 4; kk++) {
            uint32_t ah[4], al[4];
            LDSM4(ah, sb + O_QH + SOFF(qrow, kk * 2 + qch));
            LDSM4(al, sb + O_QL + SOFF(qrow, kk * 2 + qch));
#pragma unroll
            for (int j = 0; j < 8; j++) {
                int krow = j * 8 + krl;
                uint32_t so = SOFF(krow, kk * 2 + kch);
                uint32_t bhr[2], blr[2];
                LDSM2(bhr, sb + O_KH + so);
                LDSM2(blr, sb + O_KL + so);
                MMA_BF16(sacc[j], ah, bhr[0], bhr[1]);
                MMA_BF16(sacc[j], ah, blr[0], blr[1]);
                MMA_BF16(sacc[j], al, bhr[0], bhr[1]);
            }
        }

        uint32_t phA[8][2], plA[8][2];
        const float* mk = (const float*)(sm + O_MSK);
        size_t ab = ((size_t)bh * SS + q0 + w * 16) * (size_t)SS + k0;
#pragma unroll
        for (int j = 0; j < 8; j++) {
            float m0 = mk[j * 8 + t * 2], m1 = mk[j * 8 + t * 2 + 1];
            float p0 = m0 * __expf(sacc[j][0] * 0.125f) * inv0;
            float p1 = m1 * __expf(sacc[j][1] * 0.125f) * inv0;
            float p2 = m0 * __expf(sacc[j][2] * 0.125f) * inv1;
            float p3 = m1 * __expf(sacc[j][3] * 0.125f) * inv1;
            int cc = j * 8 + t * 2;
            *(float2*)&attn[ab + (size_t)g * SS + cc]       = make_float2(p0, p1);
            *(float2*)&attn[ab + (size_t)(g + 8) * SS + cc] = make_float2(p2, p3);
            split2(p0, p1, phA[j][0], plA[j][0]);
            split2(p2, p3, phA[j][1], plA[j][1]);
        }

#pragma unroll
        for (int kk2 = 0; kk2 < 4; kk2++) {
            uint32_t ah[4] = { phA[2*kk2][0], phA[2*kk2][1],
                               phA[2*kk2+1][0], phA[2*kk2+1][1] };
            uint32_t al[4] = { plA[2*kk2][0], plA[2*kk2][1],
                               plA[2*kk2+1][0], plA[2*kk2+1][1] };
            int vrow = kk2 * 16 + vrl;
#pragma unroll
            for (int nj = 0; nj < 8; nj++) {
                uint32_t so = SOFF(vrow, nj);
                uint32_t bhr[2], blr[2];
                LDSM2T(bhr, sb + O_VH + so);
                LDSM2T(blr, sb + O_VL + so);
                MMA_BF16(vacc[nj], ah, bhr[0], bhr[1]);
                MMA_BF16(vacc[nj], ah, blr[0], blr[1]);
                MMA_BF16(vacc[nj], al, bhr[0], bhr[1]);
            }
        }
    }

    // ---- epilogue: ctx -> bf16 hi/lo [B][S][D] (feeds mma O-projection) ----
    {
        size_t o0 = ((size_t)(b * SS + q0 + w * 16 + g)) * DD + h * HD;
        size_t o1 = o0 + (size_t)8 * DD;
#pragma unroll
        for (int nj = 0; nj < 8; nj++) {
            int cc = nj * 8 + t * 2;
            uint32_t hw, lw;
            split2(vacc[nj][0], vacc[nj][1], hw, lw);
            *(uint32_t*)&g_Ch[o0 + cc] = hw;
            *(uint32_t*)&g_Cl[o0 + cc] = lw;
            split2(vacc[nj][2], vacc[nj][3], hw, lw);
            *(uint32_t*)&g_Ch[o1 + cc] = hw;
            *(uint32_t*)&g_Cl[o1 + cc] = lw;
        }
    }
}

// ---------------- launch ----------------
extern "C" void kernel_launch(void* const* d_in, const int* in_sizes, int n_in,
                              void* d_out, int out_size)
{
    const float* q    = (const float*)d_in[0];
    const float* k    = (const float*)d_in[1];
    const float* v    = (const float*)d_in[2];
    const int*   mask = (const int*)  d_in[3];
    const float* Wq   = (const float*)d_in[4];
    const float* bq   = (const float*)d_in[5];
    const float* Wk   = (const float*)d_in[6];
    const float* bk   = (const float*)d_in[7];
    const float* Wv   = (const float*)d_in[8];
    const float* bv   = (const float*)d_in[9];
    const float* Wo   = (const float*)d_in[10];
    const float* bo   = (const float*)d_in[11];

    float* outx = (float*)d_out;
    float* attn = outx + X_ELEMS;

    __nv_bfloat16 *pQh, *pQl, *pKh, *pKl, *pVh, *pVl, *pCh, *pCl;
    __nv_bfloat16 *pAh, *pAl, *pWh, *pWl;
    cudaGetSymbolAddress((void**)&pQh, g_Qh);
    cudaGetSymbolAddress((void**)&pQl, g_Ql);
    cudaGetSymbolAddress((void**)&pKh, g_Kh);
    cudaGetSymbolAddress((void**)&pKl, g_Kl);
    cudaGetSymbolAddress((void**)&pVh, g_Vh);
    cudaGetSymbolAddress((void**)&pVl, g_Vl);
    cudaGetSymbolAddress((void**)&pCh, g_Ch);
    cudaGetSymbolAddress((void**)&pCl, g_Cl);
    cudaGetSymbolAddress((void**)&pAh, g_Ah);
    cudaGetSymbolAddress((void**)&pAl, g_Al);
    cudaGetSymbolAddress((void**)&pWh, g_Wh);
    cudaGetSymbolAddress((void**)&pWl, g_Wl);

    cudaFuncSetAttribute(attn_mma,
                         cudaFuncAttributeMaxDynamicSharedMemorySize, ATT_SMEM);
    cudaFuncSetAttribute(gemm_mma,
                         cudaFuncAttributeMaxDynamicSharedMemorySize, GEMM_SMEM);

    const int N4X = X_ELEMS / 4;       // input convert chunks
    const int N4W = DD * DD / 4;       // weight convert chunks
    dim3 gg(DD / 128, MROWS / 128), bt(256);

    // Q projection
    fsplit<<<(N4X + 255) / 256, 256>>>(q, pAh, pAl, N4X);
    fsplit<<<(N4W + 255) / 256, 256>>>(Wq, pWh, pWl, N4W);
    gemm_mma<<<gg, bt, GEMM_SMEM>>>(pAh, pAl, bq, nullptr, pQh, pQl, 0);
    // K projection
    fsplit<<<(N4X + 255) / 256, 256>>>(k, pAh, pAl, N4X);
    fsplit<<<(N4W + 255) / 256, 256>>>(Wk, pWh, pWl, N4W);
    gemm_mma<<<gg, bt, GEMM_SMEM>>>(pAh, pAl, bk, nullptr, pKh, pKl, 0);
    // V projection
    fsplit<<<(N4X + 255) / 256, 256>>>(v, pAh, pAl, N4X);
    fsplit<<<(N4W + 255) / 256, 256>>>(Wv, pWh, pWl, N4W);
    gemm_mma<<<gg, bt, GEMM_SMEM>>>(pAh, pAl, bv, nullptr, pVh, pVl, 0);

    // fused attention (writes attn + ctx hi/lo)
    attn_mma<<<dim3(SS / 128, BB * HH), 256, ATT_SMEM>>>(mask, attn);

    // O projection (ctx hi/lo from attention epilogue)
    fsplit<<<(N4W + 255) / 256, 256>>>(Wo, pWh, pWl, N4W);
    gemm_mma<<<gg, bt, GEMM_SMEM>>>(pCh, pCl, bo, outx, nullptr, nullptr, 1);
}

// round 16
// speedup vs baseline: 1.0681x; 1.0681x over previous
#include <cuda_runtime.h>
#include <cuda_bf16.h>
#include <cstdint>

// Problem constants
#define BB 2
#define SS 2048
#define DD 1024
#define HH 16
#define HD 64
#define MROWS (BB*SS)          // 4096
#define X_ELEMS (BB*SS*DD)     // 4194304
#define ATT_ELEMS (BB*HH*SS*SS)// 134217728

// ---------------- scratch (device globals: allocation-free) ----------------
__device__ float g_ctx[MROWS*DD];  // [B][S][D] fp32 context (input to O proj)
__device__ __nv_bfloat16 g_Qh[MROWS*DD], g_Ql[MROWS*DD]; // [BH][S][HD]
__device__ __nv_bfloat16 g_Kh[MROWS*DD], g_Kl[MROWS*DD]; // [BH][S][HD]
__device__ __nv_bfloat16 g_Vh[MROWS*DD], g_Vl[MROWS*DD]; // [BH][S][HD]

// ---------------- packed f32x2 helpers (FFMA2 path, projections) -----------
__device__ __forceinline__ unsigned long long pk2(float lo, float hi) {
    unsigned long long r;
    asm("mov.b64 %0, {%1, %2};" : "=l"(r) : "f"(lo), "f"(hi));
    return r;
}
__device__ __forceinline__ void fma2(unsigned long long &d,
                                     unsigned long long a,
                                     unsigned long long b) {
    asm("fma.rn.f32x2 %0, %1, %2, %0;" : "+l"(d) : "l"(a), "l"(b));
}
__device__ __forceinline__ float2 upk(unsigned long long v) {
    float2 f;
    asm("mov.b64 {%0, %1}, %2;" : "=f"(f.x), "=f"(f.y) : "l"(v));
    return f;
}

// ---------------- mma.sync / ldmatrix helpers (baseline ISA, sm_80+) -------
__device__ __forceinline__ uint32_t smem_u32(const void* p) {
    uint32_t a;
    asm("{ .reg .u64 t; cvta.to.shared.u64 t, %1; cvt.u32.u64 %0, t; }"
        : "=r"(a) : "l"(p));
    return a;
}
#define LDSM4(r, a)                                                          \
    asm volatile("ldmatrix.sync.aligned.m8n8.x4.shared.b16 {%0,%1,%2,%3}, [%4];" \
        : "=r"((r)[0]), "=r"((r)[1]), "=r"((r)[2]), "=r"((r)[3]) : "r"(a) : "memory")
#define LDSM4T(r, a)                                                         \
    asm volatile("ldmatrix.sync.aligned.m8n8.x4.trans.shared.b16 {%0,%1,%2,%3}, [%4];" \
        : "=r"((r)[0]), "=r"((r)[1]), "=r"((r)[2]), "=r"((r)[3]) : "r"(a) : "memory")
#define MMA_BF16(c, a, b0, b1)                                               \
    asm volatile("mma.sync.aligned.m16n8k16.row.col.f32.bf16.bf16.f32 "      \
        "{%0,%1,%2,%3}, {%4,%5,%6,%7}, {%8,%9}, {%0,%1,%2,%3};"              \
        : "+f"((c)[0]), "+f"((c)[1]), "+f"((c)[2]), "+f"((c)[3])             \
        : "r"((a)[0]), "r"((a)[1]), "r"((a)[2]), "r"((a)[3]),                \
          "r"(b0), "r"(b1))

// hi/lo bf16 split of two floats -> packed bf16x2 words
__device__ __forceinline__ void split2(float a, float b, uint32_t &h, uint32_t &l) {
    __nv_bfloat162 hb = __floats2bfloat162_rn(a, b);
    float2 hf = __bfloat1622float2(hb);
    __nv_bfloat162 lb = __floats2bfloat162_rn(a - hf.x, b - hf.y);
    h = *reinterpret_cast<uint32_t*>(&hb);
    l = *reinterpret_cast<uint32_t*>(&lb);
}

// ---------------- SGEMM (FFMA2): projections (R13 known-good) --------------
// mode 0: write bf16 hi/lo split, scattered to [B*H][S][HD] (QKV proj)
// mode 1: write fp32 plain [M][N] row-major (O proj)
__global__ __launch_bounds__(256, 2)
void sgemm128(const float* __restrict__ A, const float* __restrict__ W,
              const float* __restrict__ bias, float* __restrict__ out,
              __nv_bfloat16* __restrict__ outH, __nv_bfloat16* __restrict__ outL,
              int mode)
{
    const int K = 1024;
    __shared__ float As[8][128];
    __shared__ float Bs[8][128];

    int tid  = threadIdx.x;
    int m0   = blockIdx.y << 7;
    int n0   = blockIdx.x << 7;
    int lrow = tid >> 1;
    int lseg = (tid & 1) << 2;
    int tx   = tid & 15, ty = tid >> 4;
    int ra   = ty << 2,  cb = tx << 2;

    const float* Ag = A + (size_t)(m0 + lrow) * K + lseg;
    const float* Wg = W + (size_t)(n0 + lrow) * K + lseg;

    unsigned long long acc[8][4];
#pragma unroll
    for (int i = 0; i < 8; i++)
#pragma unroll
        for (int j = 0; j < 4; j++) acc[i][j] = 0ull;

    float4 av = *(const float4*)Ag;
    float4 wv = *(const float4*)Wg;

    for (int k0 = 0; k0 < K; k0 += 8) {
        __syncthreads();
        As[lseg+0][lrow] = av.x; As[lseg+1][lrow] = av.y;
        As[lseg+2][lrow] = av.z; As[lseg+3][lrow] = av.w;
        Bs[lseg+0][lrow] = wv.x; Bs[lseg+1][lrow] = wv.y;
        Bs[lseg+2][lrow] = wv.z; Bs[lseg+3][lrow] = wv.w;
        __syncthreads();
        if (k0 + 8 < K) {
            av = *(const float4*)(Ag + k0 + 8);
            wv = *(const float4*)(Wg + k0 + 8);
        }
#pragma unroll
        for (int kk = 0; kk < 8; kk++) {
            float af[8];
            *(float4*)(af)     = *(const float4*)&As[kk][ra];
            *(float4*)(af + 4) = *(const float4*)&As[kk][64 + ra];
            unsigned long long b2[4];
            *(ulonglong2*)(b2)     = *(const ulonglong2*)&Bs[kk][cb];
            *(ulonglong2*)(b2 + 2) = *(const ulonglong2*)&Bs[kk][64 + cb];
#pragma unroll
            for (int i = 0; i < 8; i++) {
                unsigned long long ad = pk2(af[i], af[i]);
                fma2(acc[i][0], ad, b2[0]);
                fma2(acc[i][1], ad, b2[1]);
                fma2(acc[i][2], ad, b2[2]);
                fma2(acc[i][3], ad, b2[3]);
            }
        }
    }

#pragma unroll
    for (int i = 0; i < 8; i++) {
        int r = m0 + ((i < 4) ? (ra + i) : (64 + ra + i - 4));
#pragma unroll
        for (int half = 0; half < 2; half++) {
            int c = n0 + (half ? (64 + cb) : cb);
            float2 p0 = upk(acc[i][half * 2 + 0]);
            float2 p1 = upk(acc[i][half * 2 + 1]);
            float4 v;
            v.x = p0.x + bias[c + 0];
            v.y = p0.y + bias[c + 1];
            v.z = p1.x + bias[c + 2];
            v.w = p1.y + bias[c + 3];
            if (mode == 0) {
                int b = r >> 11, s = r & 2047;
                int h = c >> 6,  hd = c & 63;
                size_t o = (((size_t)(b * HH + h) * SS) + s) * HD + hd;
                uint32_t h0, h1, l0, l1;
                split2(v.x, v.y, h0, l0);
                split2(v.z, v.w, h1, l1);
                *(uint2*)&outH[o] = make_uint2(h0, h1);
                *(uint2*)&outL[o] = make_uint2(l0, l1);
            } else {
                *(float4*)&out[(size_t)r * DD + c] = v;
            }
        }
    }
}

// ---------------- mma.sync fused attention v2 -------------------------------
// Per CTA: one (b,h), 128 q rows, 8 warps (16 q rows each), NKT=32 k-tiles.
// Pass 1: 1-product bf16 scores (Qh*Kh only) -> exp -> row sums. The 1-product
//   score error (~1.6e-3 on exp args) is zero-mean across ~2048 terms, so the
//   row-sum (normalization) error averages to ~4e-5 — well under budget.
// Pass 2: 3-product scores -> normalized attn write + 3-product PV.
// B-fragments batched: ldmatrix.x4 over K j-tile pairs, x4.trans over V pairs.
#define SOFF(row, ch) ((uint32_t)((row) * 128 + (((ch) ^ ((row) & 7)) << 4)))
#define O_QH 0
#define O_QL 16384
#define O_KH 32768
#define O_KL 40960
#define O_VH 49152
#define O_VL 57344
#define O_MSK 65536
#define ATT_SMEM (65536 + 256)
#define NKT (SS / 64)   // 32

__global__ __launch_bounds__(256, 2)
void attn_mma(const int* __restrict__ mask, float* __restrict__ attn)
{
    extern __shared__ char sm[];
    uint32_t sb = smem_u32(sm);

    int tid = threadIdx.x, w = tid >> 5, lane = tid & 31;
    int g = lane >> 2, t = lane & 3;
    int bh = blockIdx.y, b = bh >> 4, h = bh & 15;
    int q0 = blockIdx.x << 7;

    // ---- load Q tile (128 x 64 bf16 hi/lo) ----
    size_t qb = ((size_t)bh * SS + q0) * HD;
#pragma unroll
    for (int i = tid; i < 128 * 8; i += 256) {
        int r = i >> 3, c = i & 7;
        uint32_t so = SOFF(r, c);
        *(uint4*)(sm + O_QH + so) = *(const uint4*)(g_Qh + qb + r * HD + c * 8);
        *(uint4*)(sm + O_QL + so) = *(const uint4*)(g_Ql + qb + r * HD + c * 8);
    }

    // per-lane ldmatrix address components
    int qrow = w * 16 + (lane & 15);          // A-frag row (Q and P)
    int qch  = lane >> 4;                     // A-frag col-half
    int krl  = lane & 7;                      // B-frag row within 8-tile (K)
    int kch  = (lane >> 3) & 1;               // B-frag k-half (K)
    int kj2  = lane >> 4;                     // B-frag pair-select (K, x4)
    int vrl  = lane & 15;                     // B-frag row (V, trans)
    int vj2  = lane >> 4;                     // B-frag pair-select (V, x4.trans)

    float rs0 = 0.f, rs1 = 0.f;

    // =================== PASS 1: row sums (1-product scores) ===============
    for (int kt = 0; kt < NKT; kt++) {
        int k0 = kt << 6;
        size_t kb = ((size_t)bh * SS + k0) * HD;
        __syncthreads();
#pragma unroll
        for (int i = tid; i < 64 * 8; i += 256) {     // Kh only
            int r = i >> 3, c = i & 7;
            *(uint4*)(sm + O_KH + SOFF(r, c)) =
                *(const uint4*)(g_Kh + kb + r * HD + c * 8);
        }
        if (tid < 64)
            ((float*)(sm + O_MSK))[tid] = mask[b * SS + k0 + tid] ? 1.f : 0.f;
        __syncthreads();

        float sacc[8][4];
#pragma unroll
        for (int j = 0; j < 8; j++)
#pragma unroll
            for (int x = 0; x < 4; x++) sacc[j][x] = 0.f;

#pragma unroll
        for (int kk = 0; kk < 4; kk++) {
            uint32_t ah[4];
            LDSM4(ah, sb + O_QH + SOFF(qrow, kk * 2 + qch));
#pragma unroll
            for (int j = 0; j < 8; j += 2) {
                int krow = (j + kj2) * 8 + krl;
                uint32_t b4[4];
                LDSM4(b4, sb + O_KH + SOFF(krow, kk * 2 + kch));
                MMA_BF16(sacc[j],     ah, b4[0], b4[1]);
                MMA_BF16(sacc[j + 1], ah, b4[2], b4[3]);
            }
        }

        const float* mk = (const float*)(sm + O_MSK);
#pragma unroll
        for (int j = 0; j < 8; j++) {
            float m0 = mk[j * 8 + t * 2], m1 = mk[j * 8 + t * 2 + 1];
            rs0 += m0 * __expf(sacc[j][0] * 0.125f) + m1 * __expf(sacc[j][1] * 0.125f);
            rs1 += m0 * __expf(sacc[j][2] * 0.125f) + m1 * __expf(sacc[j][3] * 0.125f);
        }
    }
    // quad reduce (lanes g*4..g*4+3 share rows g / g+8)
    rs0 += __shfl_xor_sync(0xffffffffu, rs0, 1);
    rs0 += __shfl_xor_sync(0xffffffffu, rs0, 2);
    rs1 += __shfl_xor_sync(0xffffffffu, rs1, 1);
    rs1 += __shfl_xor_sync(0xffffffffu, rs1, 2);
    float inv0 = 1.f / rs0, inv1 = 1.f / rs1;

    // =================== PASS 2: normalized attn + PV (3-product) ==========
    float vacc[8][4];
#pragma unroll
    for (int j = 0; j < 8; j++)
#pragma unroll
        for (int x = 0; x < 4; x++) vacc[j][x] = 0.f;

    for (int kt = 0; kt < NKT; kt++) {
        int k0 = kt << 6;
        size_t kb = ((size_t)bh * SS + k0) * HD;
        __syncthreads();
#pragma unroll
        for (int i = tid; i < 64 * 8; i += 256) {
            int r = i >> 3, c = i & 7;
            uint32_t so = SOFF(r, c);
            *(uint4*)(sm + O_KH + so) = *(const uint4*)(g_Kh + kb + r * HD + c * 8);
            *(uint4*)(sm + O_KL + so) = *(const uint4*)(g_Kl + kb + r * HD + c * 8);
            *(uint4*)(sm + O_VH + so) = *(const uint4*)(g_Vh + kb + r * HD + c * 8);
            *(uint4*)(sm + O_VL + so) = *(const uint4*)(g_Vl + kb + r * HD + c * 8);
        }
        if (tid < 64)
            ((float*)(sm + O_MSK))[tid] = mask[b * SS + k0 + tid] ? 1.f : 0.f;
        __syncthreads();

        // ---- scores (3 products: ah*bh + ah*bl + al*bh) ----
        float sacc[8][4];
#pragma unroll
        for (int j = 0; j < 8; j++)
#pragma unroll
            for (int x = 0; x < 4; x++) sacc[j][x] = 0.f;
#pragma unroll
        for (int kk = 0; kk < 4; kk++) {
            uint32_t ah[4], al[4];
            LDSM4(ah, sb + O_QH + SOFF(qrow, kk * 2 + qch));
            LDSM4(al, sb + O_QL + SOFF(qrow, kk * 2 + qch));
#pragma unroll
            for (int j = 0; j < 8; j += 2) {
                int krow = (j + kj2) * 8 + krl;
                uint32_t so = SOFF(krow, kk * 2 + kch);
                uint32_t bh4[4], bl4[4];
                LDSM4(bh4, sb + O_KH + so);
                LDSM4(bl4, sb + O_KL + so);
                MMA_BF16(sacc[j],     ah, bh4[0], bh4[1]);
                MMA_BF16(sacc[j],     ah, bl4[0], bl4[1]);
                MMA_BF16(sacc[j],     al, bh4[0], bh4[1]);
                MMA_BF16(sacc[j + 1], ah, bh4[2], bh4[3]);
                MMA_BF16(sacc[j + 1], ah, bl4[2], bl4[3]);
                MMA_BF16(sacc[j + 1], al, bh4[2], bh4[3]);
            }
        }

        // ---- normalized p: write attn + build PV A-fragments in regs ----
        uint32_t phA[8][2], plA[8][2];
        const float* mk = (const float*)(sm + O_MSK);
        size_t ab = ((size_t)bh * SS + q0 + w * 16) * (size_t)SS + k0;
#pragma unroll
        for (int j = 0; j < 8; j++) {
            float m0 = mk[j * 8 + t * 2], m1 = mk[j * 8 + t * 2 + 1];
            float p0 = m0 * __expf(sacc[j][0] * 0.125f) * inv0;
            float p1 = m1 * __expf(sacc[j][1] * 0.125f) * inv0;
            float p2 = m0 * __expf(sacc[j][2] * 0.125f) * inv1;
            float p3 = m1 * __expf(sacc[j][3] * 0.125f) * inv1;
            int cc = j * 8 + t * 2;
            *(float2*)&attn[ab + (size_t)g * SS + cc]       = make_float2(p0, p1);
            *(float2*)&attn[ab + (size_t)(g + 8) * SS + cc] = make_float2(p2, p3);
            split2(p0, p1, phA[j][0], plA[j][0]);
            split2(p2, p3, phA[j][1], plA[j][1]);
        }

        // ---- PV: vacc += P @ V (3 products, x4.trans B pairs) ----
#pragma unroll
        for (int kk2 = 0; kk2 < 4; kk2++) {
            uint32_t ah[4] = { phA[2*kk2][0], phA[2*kk2][1],
                               phA[2*kk2+1][0], phA[2*kk2+1][1] };
            uint32_t al[4] = { plA[2*kk2][0], plA[2*kk2][1],
                               plA[2*kk2+1][0], plA[2*kk2+1][1] };
            int vrow = kk2 * 16 + vrl;
#pragma unroll
            for (int nj = 0; nj < 8; nj += 2) {
                uint32_t so = SOFF(vrow, nj + vj2);
                uint32_t bh4[4], bl4[4];
                LDSM4T(bh4, sb + O_VH + so);
                LDSM4T(bl4, sb + O_VL + so);
                MMA_BF16(vacc[nj],     ah, bh4[0], bh4[1]);
                MMA_BF16(vacc[nj],     ah, bl4[0], bl4[1]);
                MMA_BF16(vacc[nj],     al, bh4[0], bh4[1]);
                MMA_BF16(vacc[nj + 1], ah, bh4[2], bh4[3]);
                MMA_BF16(vacc[nj + 1], ah, bl4[2], bl4[3]);
                MMA_BF16(vacc[nj + 1], al, bh4[2], bh4[3]);
            }
        }
    }

    // ---- epilogue: ctx (already normalized) -> [B][S][D] fp32 ----
    {
        float* cp0 = g_ctx + ((size_t)(b * SS + q0 + w * 16 + g)) * DD + h * HD;
        float* cp1 = cp0 + (size_t)8 * DD;
#pragma unroll
        for (int nj = 0; nj < 8; nj++) {
            int cc = nj * 8 + t * 2;
            *(float2*)&cp0[cc] = make_float2(vacc[nj][0], vacc[nj][1]);
            *(float2*)&cp1[cc] = make_float2(vacc[nj][2], vacc[nj][3]);
        }
    }
}

// ---------------- launch ----------------
extern "C" void kernel_launch(void* const* d_in, const int* in_sizes, int n_in,
                              void* d_out, int out_size)
{
    const float* q    = (const float*)d_in[0];
    const float* k    = (const float*)d_in[1];
    const float* v    = (const float*)d_in[2];
    const int*   mask = (const int*)  d_in[3];
    const float* Wq   = (const float*)d_in[4];
    const float* bq   = (const float*)d_in[5];
    const float* Wk   = (const float*)d_in[6];
    const float* bk   = (const float*)d_in[7];
    const float* Wv   = (const float*)d_in[8];
    const float* bv   = (const float*)d_in[9];
    const float* Wo   = (const float*)d_in[10];
    const float* bo   = (const float*)d_in[11];

    float* outx = (float*)d_out;
    float* attn = outx + X_ELEMS;

    float* pC;
    __nv_bfloat16 *pQh, *pQl, *pKh, *pKl, *pVh, *pVl;
    cudaGetSymbolAddress((void**)&pC,  g_ctx);
    cudaGetSymbolAddress((void**)&pQh, g_Qh);
    cudaGetSymbolAddress((void**)&pQl, g_Ql);
    cudaGetSymbolAddress((void**)&pKh, g_Kh);
    cudaGetSymbolAddress((void**)&pKl, g_Kl);
    cudaGetSymbolAddress((void**)&pVh, g_Vh);
    cudaGetSymbolAddress((void**)&pVl, g_Vl);

    cudaFuncSetAttribute(attn_mma,
                         cudaFuncAttributeMaxDynamicSharedMemorySize, ATT_SMEM);

    dim3 gg(DD / 128, MROWS / 128), bt(256);
    sgemm128<<<gg, bt>>>(q, Wq, bq, nullptr, pQh, pQl, 0);
    sgemm128<<<gg, bt>>>(k, Wk, bk, nullptr, pKh, pKl, 0);
    sgemm128<<<gg, bt>>>(v, Wv, bv, nullptr, pVh, pVl, 0);

    attn_mma<<<dim3(SS / 128, BB * HH), 256, ATT_SMEM>>>(mask, attn);

    sgemm128<<<gg, bt>>>(pC, Wo, bo, outx, nullptr, nullptr, 1);
}